// round 5
// baseline (speedup 1.0000x reference)
#include <cuda_runtime.h>
#include <math.h>
#include <stdint.h>

#define B_ 64
#define T_ 512
#define F_ 64
#define U_ 128
#define G_ 512   // 4*U

// ---------------- scratch (static device memory; no allocations) ----------------
__device__ float g_mask[B_ * T_];                       // 32768
__device__ float g_zx[2u * B_ * T_ * G_];               // 33.5M floats (layer1 then layer2)
__device__ float g_h1[B_ * T_ * 2 * U_];                // layer-1 hidden concat [b][t][2U]
__device__ float g_h2[B_ * 2 * U_];                     // layer-2 final hidden concat
// packed recurrent weights: [seg][(k>>2)*2048 + col*4 + (k&3)], seg = layer*2+dir
__device__ float g_wpk[4 * G_ * U_];

// ---------------- helpers ----------------
#define FMA2(acc, a, b) asm("fma.rn.f32x2 %0, %1, %2, %0;" : "+l"(acc) : "l"(a), "l"(b))

__device__ __forceinline__ float f32x2_sum(unsigned long long v) {
    unsigned lo, hi;
    asm("mov.b64 {%0, %1}, %2;" : "=r"(lo), "=r"(hi) : "l"(v));
    return __uint_as_float(lo) + __uint_as_float(hi);
}
__device__ __forceinline__ uint32_t s2u(const void* p) {
    uint32_t a;
    asm("{ .reg .u64 t; cvta.to.shared.u64 t, %1; cvt.u32.u64 %0, t; }" : "=r"(a) : "l"(p));
    return a;
}
__device__ __forceinline__ uint32_t ctarank() {
    uint32_t r;
    asm("mov.u32 %0, %%cluster_ctarank;" : "=r"(r));
    return r;
}

// ---------------- prep: mask + weight packing ----------------
__global__ void prep_kernel(const float* __restrict__ x,
                            const float* __restrict__ w1f, const float* __restrict__ w1b,
                            const float* __restrict__ w2f, const float* __restrict__ w2b) {
    int i = blockIdx.x * blockDim.x + threadIdx.x;
    if (i < B_ * T_) {
        const float4* row = (const float4*)(x + (size_t)i * F_);
        bool nz = false;
#pragma unroll
        for (int k = 0; k < F_ / 4; k++) {
            float4 v = row[k];
            nz = nz || (v.x != 0.f) || (v.y != 0.f) || (v.z != 0.f) || (v.w != 0.f);
        }
        g_mask[i] = nz ? 1.f : 0.f;
    }
    int j = i - B_ * T_;
    if (j >= 0 && j < 4 * G_ * U_) {
        int w = j >> 16;           // which weight (0..3)
        int r = j & 65535;         // index within [128][512]
        int k = r >> 9;            // k row (0..127)
        int col = r & 511;         // gate col (0..511)
        const float* src = (w == 0) ? w1f : (w == 1) ? w1b : (w == 2) ? w2f : w2b;
        g_wpk[w * (G_ * U_) + (k >> 2) * 2048 + col * 4 + (k & 3)] = src[r];
    }
}

// ---------------- tiled fp32 GEMM with bias ----------------
__global__ __launch_bounds__(256) void sgemm_bias(
    const float* __restrict__ Aext, int useH1,
    const float* __restrict__ W, const float* __restrict__ bias,
    int dirOff, int M, int N, int K) {
    __shared__ float As[16][132];
    __shared__ float Bs[16][128];
    const float* A = useH1 ? g_h1 : Aext;
    float* C = g_zx + (size_t)dirOff * B_ * T_ * G_;

    int tid = threadIdx.x;
    int nBase = blockIdx.x * 128;
    int mBase = blockIdx.y * 128;
    int tx = tid & 15, ty = tid >> 4;
    float acc[8][8];
#pragma unroll
    for (int i = 0; i < 8; i++)
#pragma unroll
        for (int j = 0; j < 8; j++) acc[i][j] = 0.f;

    for (int k0 = 0; k0 < K; k0 += 16) {
#pragma unroll
        for (int s = 0; s < 2; s++) {
            int slot = tid + s * 256;
            int row = slot >> 2, c4 = slot & 3;
            float4 v = *(const float4*)(A + (size_t)(mBase + row) * K + k0 + c4 * 4);
            As[c4 * 4 + 0][row] = v.x;
            As[c4 * 4 + 1][row] = v.y;
            As[c4 * 4 + 2][row] = v.z;
            As[c4 * 4 + 3][row] = v.w;
        }
#pragma unroll
        for (int s = 0; s < 2; s++) {
            int slot = tid + s * 256;
            int row = slot >> 5, c4 = slot & 31;
            *(float4*)(&Bs[row][c4 * 4]) =
                *(const float4*)(W + (size_t)(k0 + row) * N + nBase + c4 * 4);
        }
        __syncthreads();
#pragma unroll
        for (int k = 0; k < 16; k++) {
            float a[8], b[8];
            *(float4*)(a)     = *(const float4*)&As[k][ty * 8];
            *(float4*)(a + 4) = *(const float4*)&As[k][ty * 8 + 4];
            *(float4*)(b)     = *(const float4*)&Bs[k][tx * 8];
            *(float4*)(b + 4) = *(const float4*)&Bs[k][tx * 8 + 4];
#pragma unroll
            for (int i = 0; i < 8; i++)
#pragma unroll
                for (int j = 0; j < 8; j++) acc[i][j] = fmaf(a[i], b[j], acc[i][j]);
        }
        __syncthreads();
    }
#pragma unroll
    for (int i = 0; i < 8; i++) {
        int row = mBase + ty * 8 + i;
#pragma unroll
        for (int j = 0; j < 8; j += 4) {
            int col = nBase + tx * 8 + j;
            float4 o;
            o.x = acc[i][j + 0] + bias[col + 0];
            o.y = acc[i][j + 1] + bias[col + 1];
            o.z = acc[i][j + 2] + bias[col + 2];
            o.w = acc[i][j + 3] + bias[col + 3];
            *(float4*)(C + (size_t)row * N + col) = o;
        }
    }
}

// ---------------- recurrent LSTM scan: cluster-2, reg weights, 2 batch-pairs ----------------
// 64 CTAs, cluster (2,1,1) -> 32 clusters. cid = blockIdx.x>>1: dir = cid>>4,
// qb = (cid&15)*4 -> batches qb..qb+3 (pair A = qb,qb+1 ; pair B = qb+2,qb+3).
// 512 threads; pr = tid>>8 selects pair (and doubles as matvec k-half kh):
//   matvec: all threads, 4 batches, col c = tid&255 (gc = rank*256+c), k-half kh=pr
//   writer+elementwise: group pr handles its own pair only (named barrier 1+pr).
// Weights register-resident (shared across batches). Gates exchanged across the
// cluster per pair via st.shared::cluster + per-pair double-buffered mbarriers;
// pair A's exchange latency overlaps pair B's compute and vice versa.
__global__ __launch_bounds__(512, 1) __cluster_dims__(2, 1, 1)
void lstm_scan(int layer) {
    int tid = threadIdx.x;
    uint32_t rank = ctarank();
    uint32_t peer = rank ^ 1u;
    int cid = blockIdx.x >> 1;
    int dir = cid >> 4;
    int qb = (cid & 15) * 4;

    __shared__ __align__(16) float sh_h[4][128];            // [batch 0..3][u]
    __shared__ __align__(16) float4 sh_part[2][256];        // [kh][c] = (A0,A1,B0,B1)
    __shared__ __align__(16) float gbuf[2][2][512][2];      // [pr][par][gc][batch-in-pair]
    __shared__ __align__(8) unsigned long long mbar[4];     // [pr*2+par]

    int pr = tid >> 8;          // pair id; also k-half for matvec
    int c = tid & 255;
    int gc = (int)rank * 256 + c;
    int seg = layer * 2 + dir;

    // ---- load this thread's 64 weights into registers (once) ----
    ulonglong2 warr[16];
    {
        const float* wb = g_wpk + (size_t)seg * 65536 + (size_t)(16 * pr) * 2048 + gc * 4;
#pragma unroll
        for (int i = 0; i < 16; i++) warr[i] = *(const ulonglong2*)(wb + i * 2048);
    }

    uint32_t mbarAddr[4];
#pragma unroll
    for (int i = 0; i < 4; i++) mbarAddr[i] = s2u(&mbar[i]);
    uint32_t gbufBase = s2u(&gbuf[0][0][0][0]);

    if (tid < 4) {
        asm volatile("mbarrier.init.shared.b64 [%0], %1;"
                     :: "r"(mbarAddr[tid]), "r"(256) : "memory");
    }
    sh_h[tid >> 7][tid & 127] = 0.f;    // 512 = 4*128 exactly
    __syncthreads();
    asm volatile("barrier.cluster.arrive.aligned;" ::: "memory");
    asm volatile("barrier.cluster.wait.aligned;" ::: "memory");

    // elementwise identity: unit eu of batch (qb + pr*2 + eb)
    int eu = tid & 127, eb = (tid >> 7) & 1;
    int bi = pr * 2 + eb;               // sh_h row
    float c_state = 0.f;

    // writer z prefetch: col gc, both batches of this thread's pair
    const float* zcol = g_zx + ((size_t)dir * B_ + (qb + pr * 2)) * T_ * G_ + gc;
    const int maskIdx0 = (qb + pr * 2 + eb) * T_;
    float zpre0, zpre1, mpre;
    {
        int te0 = dir ? (T_ - 1) : 0;
        zpre0 = zcol[(size_t)te0 * G_];
        zpre1 = zcol[(size_t)T_ * G_ + (size_t)te0 * G_];
        mpre = g_mask[maskIdx0 + te0];
    }

    const float* hp = &sh_h[0][64 * pr];

    for (int t = 0; t < T_; t++) {
        int te = dir ? (T_ - 1 - t) : t;

        // ---- matvec: 4 batches x own 256 cols x own k-half, weights in regs ----
        unsigned long long a0 = 0ull, a1 = 0ull, a2 = 0ull, a3 = 0ull;
#pragma unroll
        for (int i = 0; i < 16; i++) {
            ulonglong2 w = warr[i];
            ulonglong2 h0 = *(const ulonglong2*)(hp + i * 4);
            ulonglong2 h1 = *(const ulonglong2*)(hp + 128 + i * 4);
            ulonglong2 h2 = *(const ulonglong2*)(hp + 256 + i * 4);
            ulonglong2 h3 = *(const ulonglong2*)(hp + 384 + i * 4);
            FMA2(a0, w.x, h0.x); FMA2(a0, w.y, h0.y);
            FMA2(a1, w.x, h1.x); FMA2(a1, w.y, h1.y);
            FMA2(a2, w.x, h2.x); FMA2(a2, w.y, h2.y);
            FMA2(a3, w.x, h3.x); FMA2(a3, w.y, h3.y);
        }
        sh_part[pr][c] = make_float4(f32x2_sum(a0), f32x2_sum(a1),
                                     f32x2_sum(a2), f32x2_sum(a3));
        __syncthreads();

        int par = t & 1;
        int mi = pr * 2 + par;
        {
            // combine k-halves + zx bias for own pair; publish to own + peer gbuf
            float4 pa = sh_part[0][c], pb = sh_part[1][c];
            float z0, z1;
            if (pr == 0) { z0 = zpre0 + pa.x + pb.x; z1 = zpre1 + pa.y + pb.y; }
            else         { z0 = zpre0 + pa.z + pb.z; z1 = zpre1 + pa.w + pb.w; }
            gbuf[pr][par][gc][0] = z0;
            gbuf[pr][par][gc][1] = z1;
            unsigned long long pkt;
            asm("mov.b64 %0, {%1, %2};" : "=l"(pkt)
                : "r"(__float_as_uint(z0)), "r"(__float_as_uint(z1)));
            uint32_t laddr = gbufBase + (uint32_t)(((pr * 2 + par) * 512 + gc)) * 8u;
            asm volatile(
                "{ .reg .b32 ra; mapa.shared::cluster.u32 ra, %0, %1; "
                "st.shared::cluster.b64 [ra], %2; }"
                :: "r"(laddr), "r"(peer), "l"(pkt) : "memory");
            uint32_t mb = mbarAddr[mi];
            asm volatile(
                "{ .reg .b32 ra; mapa.shared::cluster.u32 ra, %0, %1; "
                "mbarrier.arrive.release.cluster.shared::cluster.b64 _, [ra]; }"
                :: "r"(mb), "r"(peer) : "memory");

            // prefetch next step's z/mask (hides latency behind peer wait)
            float nz0 = 0.f, nz1 = 0.f, nm = 0.f;
            if (t + 1 < T_) {
                int tn = dir ? (T_ - 2 - t) : (t + 1);
                nz0 = zcol[(size_t)tn * G_];
                nz1 = zcol[(size_t)T_ * G_ + (size_t)tn * G_];
                nm = g_mask[maskIdx0 + tn];
            }

            // own-half gbuf visibility within this pair group (8 warps)
            if (pr == 0) asm volatile("bar.sync 1, 256;" ::: "memory");
            else         asm volatile("bar.sync 2, 256;" ::: "memory");

            // wait for peer half (acquire, cluster scope)
            uint32_t parity = (uint32_t)((t >> 1) & 1);
            uint32_t done;
            asm volatile(
                "{\n\t.reg .pred P;\n\t"
                "mbarrier.try_wait.parity.acquire.cluster.shared::cta.b64 P, [%1], %2;\n\t"
                "selp.b32 %0, 1, 0, P;\n\t}"
                : "=r"(done) : "r"(mb), "r"(parity) : "memory");
            if (!done) {
                asm volatile(
                    "{\n\t.reg .pred P;\n"
                    "LW%=:\n\t"
                    "mbarrier.try_wait.parity.acquire.cluster.shared::cta.b64 P, [%0], %1, 0x989680;\n\t"
                    "@!P bra LW%=;\n\t}"
                    :: "r"(mb), "r"(parity) : "memory");
            }

            // ---- elementwise LSTM cell for own (batch, unit); redundant across CTAs ----
            float vi = gbuf[pr][par][eu][eb];
            float vf = gbuf[pr][par][128 + eu][eb];
            float vg = gbuf[pr][par][256 + eu][eb];
            float vo = gbuf[pr][par][384 + eu][eb];
            float si = 1.f / (1.f + __expf(-vi));
            float sf = 1.f / (1.f + __expf(-vf));
            float so = 1.f / (1.f + __expf(-vo));
            float cn = sf * c_state + si * tanhf(vg);
            float hn = so * tanhf(cn);
            float hprev = sh_h[bi][eu];
            bool mm = (mpre != 0.f);
            c_state = mm ? cn : c_state;
            float hnew = mm ? hn : hprev;
            sh_h[bi][eu] = hnew;
            if (layer == 0 && rank == 0)
                g_h1[((size_t)(qb + bi) * T_ + te) * (2 * U_) + dir * U_ + eu] = hnew;
            zpre0 = nz0; zpre1 = nz1; mpre = nm;
        }
        __syncthreads();
    }

    if (layer == 1 && rank == 0)
        g_h2[(qb + bi) * (2 * U_) + dir * U_ + eu] = sh_h[bi][eu];

    asm volatile("barrier.cluster.arrive.aligned;" ::: "memory");
    asm volatile("barrier.cluster.wait.aligned;" ::: "memory");
}

// ---------------- head: out = sigmoid(relu(h2 @ Wd + bd) @ Ws + bs) ----------------
__global__ __launch_bounds__(128) void head_kernel(
    const float* __restrict__ Wd, const float* __restrict__ bd,
    const float* __restrict__ Ws, const float* __restrict__ bs,
    float* __restrict__ out) {
    int b = blockIdx.x, u = threadIdx.x;
    float acc = bd[u];
    const float* h2 = g_h2 + b * (2 * U_);
#pragma unroll 8
    for (int j = 0; j < 2 * U_; j++) acc = fmaf(h2[j], Wd[j * U_ + u], acc);
    acc = fmaxf(acc, 0.f);
    float s = acc * Ws[u];
    __shared__ float red[128];
    red[u] = s;
    __syncthreads();
    for (int off = 64; off; off >>= 1) {
        if (u < off) red[u] += red[u + off];
        __syncthreads();
    }
    if (u == 0) out[b] = 1.f / (1.f + expf(-(red[0] + bs[0])));
}

// ---------------- launch ----------------
extern "C" void kernel_launch(void* const* d_in, const int* in_sizes, int n_in,
                              void* d_out, int out_size) {
    const float* x    = (const float*)d_in[0];
    const float* W1fi = (const float*)d_in[1];
    const float* W1fh = (const float*)d_in[2];
    const float* b1f  = (const float*)d_in[3];
    const float* W1bi = (const float*)d_in[4];
    const float* W1bh = (const float*)d_in[5];
    const float* b1b  = (const float*)d_in[6];
    const float* W2fi = (const float*)d_in[7];
    const float* W2fh = (const float*)d_in[8];
    const float* b2f  = (const float*)d_in[9];
    const float* W2bi = (const float*)d_in[10];
    const float* W2bh = (const float*)d_in[11];
    const float* b2b  = (const float*)d_in[12];
    const float* Wd   = (const float*)d_in[13];
    const float* bd   = (const float*)d_in[14];
    const float* Ws   = (const float*)d_in[15];
    const float* bs   = (const float*)d_in[16];

    int prepWork = B_ * T_ + 4 * G_ * U_;
    prep_kernel<<<(prepWork + 255) / 256, 256>>>(x, W1fh, W1bh, W2fh, W2bh);

    dim3 ggrid(G_ / 128, (B_ * T_) / 128);  // (4, 256)

    // layer-1 input projections
    sgemm_bias<<<ggrid, 256>>>(x, 0, W1fi, b1f, 0, B_ * T_, G_, F_);
    sgemm_bias<<<ggrid, 256>>>(x, 0, W1bi, b1b, 1, B_ * T_, G_, F_);
    lstm_scan<<<64, 512>>>(0);

    // layer-2 input projections (reuse g_zx)
    sgemm_bias<<<ggrid, 256>>>(nullptr, 1, W2fi, b2f, 0, B_ * T_, G_, 2 * U_);
    sgemm_bias<<<ggrid, 256>>>(nullptr, 1, W2bi, b2b, 1, B_ * T_, G_, 2 * U_);
    lstm_scan<<<64, 512>>>(1);

    head_kernel<<<64, 128>>>(Wd, bd, Ws, bs, (float*)d_out);
}

// round 6
// speedup vs baseline: 1.3728x; 1.3728x over previous
#include <cuda_runtime.h>
#include <math.h>
#include <stdint.h>

#define B_ 64
#define T_ 512
#define F_ 64
#define U_ 128
#define G_ 512   // 4*U

// ---------------- scratch (static device memory; no allocations) ----------------
__device__ float g_mask[B_ * T_];                       // 32768
__device__ float g_zx[2u * B_ * T_ * G_];               // layer1 then layer2 (reused)
__device__ float g_h1[B_ * T_ * 2 * U_];                // layer-1 hidden concat [b][t][2U]
__device__ float g_h2[B_ * 2 * U_];                     // layer-2 final hidden concat
// packed recurrent weights: [seg][(k>>2)*2048 + col*4 + (k&3)], seg = layer*2+dir
__device__ float g_wpk[4 * G_ * U_];

// ---------------- helpers ----------------
#define FMA2(acc, a, b) asm("fma.rn.f32x2 %0, %1, %2, %0;" : "+l"(acc) : "l"(a), "l"(b))

__device__ __forceinline__ float f32x2_sum(unsigned long long v) {
    unsigned lo, hi;
    asm("mov.b64 {%0, %1}, %2;" : "=r"(lo), "=r"(hi) : "l"(v));
    return __uint_as_float(lo) + __uint_as_float(hi);
}

// ---------------- prep: mask + weight packing ----------------
__global__ void prep_kernel(const float* __restrict__ x,
                            const float* __restrict__ w1f, const float* __restrict__ w1b,
                            const float* __restrict__ w2f, const float* __restrict__ w2b) {
    int i = blockIdx.x * blockDim.x + threadIdx.x;
    if (i < B_ * T_) {
        const float4* row = (const float4*)(x + (size_t)i * F_);
        bool nz = false;
#pragma unroll
        for (int k = 0; k < F_ / 4; k++) {
            float4 v = row[k];
            nz = nz || (v.x != 0.f) || (v.y != 0.f) || (v.z != 0.f) || (v.w != 0.f);
        }
        g_mask[i] = nz ? 1.f : 0.f;
    }
    int j = i - B_ * T_;
    if (j >= 0 && j < 4 * G_ * U_) {
        int w = j >> 16;           // which weight (0..3)
        int r = j & 65535;         // index within [128][512]
        int k = r >> 9;            // k row (0..127)
        int col = r & 511;         // gate col (0..511)
        const float* src = (w == 0) ? w1f : (w == 1) ? w1b : (w == 2) ? w2f : w2b;
        g_wpk[w * (G_ * U_) + (k >> 2) * 2048 + col * 4 + (k & 3)] = src[r];
    }
}

// ---------------- tiled fp32 GEMM with bias ----------------
__global__ __launch_bounds__(256) void sgemm_bias(
    const float* __restrict__ Aext, int useH1,
    const float* __restrict__ W, const float* __restrict__ bias,
    int dirOff, int M, int N, int K) {
    __shared__ float As[16][132];
    __shared__ float Bs[16][128];
    const float* A = useH1 ? g_h1 : Aext;
    float* C = g_zx + (size_t)dirOff * B_ * T_ * G_;

    int tid = threadIdx.x;
    int nBase = blockIdx.x * 128;
    int mBase = blockIdx.y * 128;
    int tx = tid & 15, ty = tid >> 4;
    float acc[8][8];
#pragma unroll
    for (int i = 0; i < 8; i++)
#pragma unroll
        for (int j = 0; j < 8; j++) acc[i][j] = 0.f;

    for (int k0 = 0; k0 < K; k0 += 16) {
#pragma unroll
        for (int s = 0; s < 2; s++) {
            int slot = tid + s * 256;
            int row = slot >> 2, c4 = slot & 3;
            float4 v = *(const float4*)(A + (size_t)(mBase + row) * K + k0 + c4 * 4);
            As[c4 * 4 + 0][row] = v.x;
            As[c4 * 4 + 1][row] = v.y;
            As[c4 * 4 + 2][row] = v.z;
            As[c4 * 4 + 3][row] = v.w;
        }
#pragma unroll
        for (int s = 0; s < 2; s++) {
            int slot = tid + s * 256;
            int row = slot >> 5, c4 = slot & 31;
            *(float4*)(&Bs[row][c4 * 4]) =
                *(const float4*)(W + (size_t)(k0 + row) * N + nBase + c4 * 4);
        }
        __syncthreads();
#pragma unroll
        for (int k = 0; k < 16; k++) {
            float a[8], b[8];
            *(float4*)(a)     = *(const float4*)&As[k][ty * 8];
            *(float4*)(a + 4) = *(const float4*)&As[k][ty * 8 + 4];
            *(float4*)(b)     = *(const float4*)&Bs[k][tx * 8];
            *(float4*)(b + 4) = *(const float4*)&Bs[k][tx * 8 + 4];
#pragma unroll
            for (int i = 0; i < 8; i++)
#pragma unroll
                for (int j = 0; j < 8; j++) acc[i][j] = fmaf(a[i], b[j], acc[i][j]);
        }
        __syncthreads();
    }
#pragma unroll
    for (int i = 0; i < 8; i++) {
        int row = mBase + ty * 8 + i;
#pragma unroll
        for (int j = 0; j < 8; j += 4) {
            int col = nBase + tx * 8 + j;
            float4 o;
            o.x = acc[i][j + 0] + bias[col + 0];
            o.y = acc[i][j + 1] + bias[col + 1];
            o.z = acc[i][j + 2] + bias[col + 2];
            o.w = acc[i][j + 3] + bias[col + 3];
            *(float4*)(C + (size_t)row * N + col) = o;
        }
    }
}

// ---------------- recurrent LSTM scan: 1 CTA per sequence, no cluster ----------------
// 128 CTAs: dir = blk>>6, b = blk&63. 512 threads, one gate column each.
// Weights k 0..63 register-resident (64 regs), k 64..127 in dynamic smem
// (streamed via conflict-free LDS.128). No partial reduction, no cross-CTA traffic.
extern __shared__ float swgt[];   // [16][512][4] = 128 KB (k4 16..31 of this seg)

__global__ __launch_bounds__(512, 1) void lstm_scan(int layer) {
    int tid = threadIdx.x;
    int dir = blockIdx.x >> 6;
    int b = blockIdx.x & 63;
    int seg = layer * 2 + dir;

    __shared__ __align__(16) float sh_h[128];
    __shared__ __align__(16) float gbuf[512];

    // ---- stage smem weight half (k 64..127 = contiguous floats [32768,65536) of seg) ----
    {
        const float4* src = (const float4*)(g_wpk + (size_t)seg * 65536 + 32768);
        float4* dst = (float4*)swgt;
        for (int j = tid; j < 8192; j += 512) dst[j] = src[j];
    }
    // ---- register weight half (k 0..63) ----
    ulonglong2 warr[16];
    {
        const float* wb = g_wpk + (size_t)seg * 65536 + tid * 4;
#pragma unroll
        for (int i = 0; i < 16; i++) warr[i] = *(const ulonglong2*)(wb + i * 2048);
    }
    if (tid < 128) sh_h[tid] = 0.f;
    __syncthreads();

    // z column pointer for this thread's gate col; prefetch first step
    const float* zcol = g_zx + ((size_t)dir * B_ + b) * T_ * G_ + tid;
    const int mbase = b * T_;
    float zpre, mpre = 0.f;
    {
        int te0 = dir ? (T_ - 1) : 0;
        zpre = zcol[(size_t)te0 * G_];
        if (tid < 128) mpre = g_mask[mbase + te0];
    }
    float c_state = 0.f;

    for (int t = 0; t < T_; t++) {
        int te = dir ? (T_ - 1 - t) : t;

        // prefetch next step's z (+mask) — consumed ~a full matvec later
        float znext = 0.f, mnext = 0.f;
        if (t + 1 < T_) {
            int tn = dir ? (T_ - 2 - t) : (t + 1);
            znext = zcol[(size_t)tn * G_];
            if (tid < 128) mnext = g_mask[mbase + tn];
        }

        // ---- matvec: full 128-k dot for own column ----
        unsigned long long acc = 0ull;
        const float* swp = swgt + tid * 4;
#pragma unroll
        for (int i = 0; i < 16; i++) {
            ulonglong2 w = warr[i];
            ulonglong2 h = *(const ulonglong2*)(sh_h + i * 4);
            FMA2(acc, w.x, h.x);
            FMA2(acc, w.y, h.y);
        }
#pragma unroll
        for (int i = 0; i < 16; i++) {
            ulonglong2 w = *(const ulonglong2*)(swp + i * 2048);
            ulonglong2 h = *(const ulonglong2*)(sh_h + 64 + i * 4);
            FMA2(acc, w.x, h.x);
            FMA2(acc, w.y, h.y);
        }
        gbuf[tid] = zpre + f32x2_sum(acc);
        __syncthreads();

        // ---- elementwise LSTM cell (threads 0..127 = units) ----
        if (tid < 128) {
            float vi = gbuf[tid];
            float vf = gbuf[128 + tid];
            float vg = gbuf[256 + tid];
            float vo = gbuf[384 + tid];
            float si = 1.f / (1.f + __expf(-vi));
            float sf = 1.f / (1.f + __expf(-vf));
            float so = 1.f / (1.f + __expf(-vo));
            float cn = sf * c_state + si * tanhf(vg);
            float hn = so * tanhf(cn);
            float hprev = sh_h[tid];
            bool mm = (mpre != 0.f);
            c_state = mm ? cn : c_state;
            float hnew = mm ? hn : hprev;
            sh_h[tid] = hnew;
            if (layer == 0)
                g_h1[((size_t)(b) * T_ + te) * (2 * U_) + dir * U_ + tid] = hnew;
        }
        zpre = znext; mpre = mnext;
        __syncthreads();
    }

    if (layer == 1 && tid < 128)
        g_h2[b * (2 * U_) + dir * U_ + tid] = sh_h[tid];
}

// ---------------- head: out = sigmoid(relu(h2 @ Wd + bd) @ Ws + bs) ----------------
__global__ __launch_bounds__(128) void head_kernel(
    const float* __restrict__ Wd, const float* __restrict__ bd,
    const float* __restrict__ Ws, const float* __restrict__ bs,
    float* __restrict__ out) {
    int b = blockIdx.x, u = threadIdx.x;
    float acc = bd[u];
    const float* h2 = g_h2 + b * (2 * U_);
#pragma unroll 8
    for (int j = 0; j < 2 * U_; j++) acc = fmaf(h2[j], Wd[j * U_ + u], acc);
    acc = fmaxf(acc, 0.f);
    float s = acc * Ws[u];
    __shared__ float red[128];
    red[u] = s;
    __syncthreads();
    for (int off = 64; off; off >>= 1) {
        if (u < off) red[u] += red[u + off];
        __syncthreads();
    }
    if (u == 0) out[b] = 1.f / (1.f + expf(-(red[0] + bs[0])));
}

// ---------------- launch ----------------
extern "C" void kernel_launch(void* const* d_in, const int* in_sizes, int n_in,
                              void* d_out, int out_size) {
    const float* x    = (const float*)d_in[0];
    const float* W1fi = (const float*)d_in[1];
    const float* W1fh = (const float*)d_in[2];
    const float* b1f  = (const float*)d_in[3];
    const float* W1bi = (const float*)d_in[4];
    const float* W1bh = (const float*)d_in[5];
    const float* b1b  = (const float*)d_in[6];
    const float* W2fi = (const float*)d_in[7];
    const float* W2fh = (const float*)d_in[8];
    const float* b2f  = (const float*)d_in[9];
    const float* W2bi = (const float*)d_in[10];
    const float* W2bh = (const float*)d_in[11];
    const float* b2b  = (const float*)d_in[12];
    const float* Wd   = (const float*)d_in[13];
    const float* bd   = (const float*)d_in[14];
    const float* Ws   = (const float*)d_in[15];
    const float* bs   = (const float*)d_in[16];

    const int SWB = 16 * 2048 * 4;   // 128 KB dynamic smem for weight half
    static int attrDone = 0;
    if (!attrDone) {
        cudaFuncSetAttribute(lstm_scan, cudaFuncAttributeMaxDynamicSharedMemorySize, SWB);
        attrDone = 1;
    }

    int prepWork = B_ * T_ + 4 * G_ * U_;
    prep_kernel<<<(prepWork + 255) / 256, 256>>>(x, W1fh, W1bh, W2fh, W2bh);

    dim3 ggrid(G_ / 128, (B_ * T_) / 128);  // (4, 256)

    // layer-1 input projections
    sgemm_bias<<<ggrid, 256>>>(x, 0, W1fi, b1f, 0, B_ * T_, G_, F_);
    sgemm_bias<<<ggrid, 256>>>(x, 0, W1bi, b1b, 1, B_ * T_, G_, F_);
    lstm_scan<<<128, 512, SWB>>>(0);

    // layer-2 input projections (reuse g_zx)
    sgemm_bias<<<ggrid, 256>>>(nullptr, 1, W2fi, b2f, 0, B_ * T_, G_, 2 * U_);
    sgemm_bias<<<ggrid, 256>>>(nullptr, 1, W2bi, b2b, 1, B_ * T_, G_, 2 * U_);
    lstm_scan<<<128, 512, SWB>>>(1);

    head_kernel<<<64, 128>>>(Wd, bd, Ws, bs, (float*)d_out);
}

// round 7
// speedup vs baseline: 1.4579x; 1.0620x over previous
#include <cuda_runtime.h>
#include <math.h>
#include <stdint.h>

#define B_ 64
#define T_ 512
#define F_ 64
#define U_ 128
#define G_ 512   // 4*U

#define RG 20    // weight k-groups in registers (k 0..79)
#define SG 12    // weight k-groups in smem    (k 80..127)

// ---------------- scratch (static device memory; no allocations) ----------------
__device__ float g_mask[B_ * T_];
__device__ float g_zx[2u * B_ * T_ * G_];               // layer1 then layer2 (reused)
__device__ float g_h1[B_ * T_ * 2 * U_];
__device__ float g_h2[B_ * 2 * U_];
// packed recurrent weights: [seg][(k>>2)*2048 + col*4 + (k&3)], seg = layer*2+dir
__device__ float g_wpk[4 * G_ * U_];

// ---------------- helpers ----------------
#define FMA2(acc, a, b) asm("fma.rn.f32x2 %0, %1, %2, %0;" : "+l"(acc) : "l"(a), "l"(b))
#define ADD2(d, a, b) asm("add.rn.f32x2 %0, %1, %2;" : "=l"(d) : "l"(a), "l"(b))

__device__ __forceinline__ float f32x2_sum(unsigned long long v) {
    unsigned lo, hi;
    asm("mov.b64 {%0, %1}, %2;" : "=r"(lo), "=r"(hi) : "l"(v));
    return __uint_as_float(lo) + __uint_as_float(hi);
}

// ---------------- prep: mask + weight packing ----------------
__global__ void prep_kernel(const float* __restrict__ x,
                            const float* __restrict__ w1f, const float* __restrict__ w1b,
                            const float* __restrict__ w2f, const float* __restrict__ w2b) {
    int i = blockIdx.x * blockDim.x + threadIdx.x;
    if (i < B_ * T_) {
        const float4* row = (const float4*)(x + (size_t)i * F_);
        bool nz = false;
#pragma unroll
        for (int k = 0; k < F_ / 4; k++) {
            float4 v = row[k];
            nz = nz || (v.x != 0.f) || (v.y != 0.f) || (v.z != 0.f) || (v.w != 0.f);
        }
        g_mask[i] = nz ? 1.f : 0.f;
    }
    int j = i - B_ * T_;
    if (j >= 0 && j < 4 * G_ * U_) {
        int w = j >> 16;
        int r = j & 65535;
        int k = r >> 9;
        int col = r & 511;
        const float* src = (w == 0) ? w1f : (w == 1) ? w1b : (w == 2) ? w2f : w2b;
        g_wpk[w * (G_ * U_) + (k >> 2) * 2048 + col * 4 + (k & 3)] = src[r];
    }
}

// ---------------- tiled fp32 GEMM with bias: f32x2 math + reg-prefetch pipeline ----------------
__global__ __launch_bounds__(256) void sgemm_bias(
    const float* __restrict__ Aext, int useH1,
    const float* __restrict__ W, const float* __restrict__ bias,
    int dirOff, int M, int N, int K) {
    __shared__ float As[16][132];
    __shared__ float Bs[16][128];
    const float* A = useH1 ? g_h1 : Aext;
    float* C = g_zx + (size_t)dirOff * B_ * T_ * G_;

    int tid = threadIdx.x;
    int nBase = blockIdx.x * 128;
    int mBase = blockIdx.y * 128;
    int tx = tid & 15, ty = tid >> 4;

    // load slots
    int aRow0 = tid >> 2, aC4 = tid & 3;
    int aRow1 = (tid + 256) >> 2;
    int bRow0 = tid >> 5, bC4 = tid & 31;
    int bRow1 = (tid + 256) >> 5;

    unsigned long long acc2[8][4];
#pragma unroll
    for (int i = 0; i < 8; i++)
#pragma unroll
        for (int j = 0; j < 4; j++) acc2[i][j] = 0ull;

    // prologue: LDG tile 0 into regs
    float4 pa0 = *(const float4*)(A + (size_t)(mBase + aRow0) * K + aC4 * 4);
    float4 pa1 = *(const float4*)(A + (size_t)(mBase + aRow1) * K + aC4 * 4);
    float4 pb0 = *(const float4*)(W + (size_t)bRow0 * N + nBase + bC4 * 4);
    float4 pb1 = *(const float4*)(W + (size_t)bRow1 * N + nBase + bC4 * 4);

    int KT = K >> 4;
    for (int kt = 0; kt < KT; kt++) {
        // STS current tile
        As[aC4 * 4 + 0][aRow0] = pa0.x;
        As[aC4 * 4 + 1][aRow0] = pa0.y;
        As[aC4 * 4 + 2][aRow0] = pa0.z;
        As[aC4 * 4 + 3][aRow0] = pa0.w;
        As[aC4 * 4 + 0][aRow1] = pa1.x;
        As[aC4 * 4 + 1][aRow1] = pa1.y;
        As[aC4 * 4 + 2][aRow1] = pa1.z;
        As[aC4 * 4 + 3][aRow1] = pa1.w;
        *(float4*)(&Bs[bRow0][bC4 * 4]) = pb0;
        *(float4*)(&Bs[bRow1][bC4 * 4]) = pb1;
        __syncthreads();

        // LDG next tile (latency hidden by compute below)
        if (kt + 1 < KT) {
            int k0 = (kt + 1) * 16;
            pa0 = *(const float4*)(A + (size_t)(mBase + aRow0) * K + k0 + aC4 * 4);
            pa1 = *(const float4*)(A + (size_t)(mBase + aRow1) * K + k0 + aC4 * 4);
            pb0 = *(const float4*)(W + (size_t)(k0 + bRow0) * N + nBase + bC4 * 4);
            pb1 = *(const float4*)(W + (size_t)(k0 + bRow1) * N + nBase + bC4 * 4);
        }

#pragma unroll
        for (int k = 0; k < 16; k++) {
            float a[8];
            *(float4*)(a)     = *(const float4*)&As[k][ty * 8];
            *(float4*)(a + 4) = *(const float4*)&As[k][ty * 8 + 4];
            ulonglong2 b01 = *(const ulonglong2*)&Bs[k][tx * 8];
            ulonglong2 b23 = *(const ulonglong2*)&Bs[k][tx * 8 + 4];
#pragma unroll
            for (int i = 0; i < 8; i++) {
                unsigned long long aa;
                unsigned au = __float_as_uint(a[i]);
                asm("mov.b64 %0, {%1, %1};" : "=l"(aa) : "r"(au));
                FMA2(acc2[i][0], aa, b01.x);
                FMA2(acc2[i][1], aa, b01.y);
                FMA2(acc2[i][2], aa, b23.x);
                FMA2(acc2[i][3], aa, b23.y);
            }
        }
        __syncthreads();
    }

#pragma unroll
    for (int i = 0; i < 8; i++) {
        int row = mBase + ty * 8 + i;
#pragma unroll
        for (int jp = 0; jp < 4; jp += 2) {
            int col = nBase + tx * 8 + jp * 2;
            unsigned lo0, hi0, lo1, hi1;
            asm("mov.b64 {%0, %1}, %2;" : "=r"(lo0), "=r"(hi0) : "l"(acc2[i][jp]));
            asm("mov.b64 {%0, %1}, %2;" : "=r"(lo1), "=r"(hi1) : "l"(acc2[i][jp + 1]));
            float4 o;
            o.x = __uint_as_float(lo0) + bias[col + 0];
            o.y = __uint_as_float(hi0) + bias[col + 1];
            o.z = __uint_as_float(lo1) + bias[col + 2];
            o.w = __uint_as_float(hi1) + bias[col + 3];
            *(float4*)(C + (size_t)row * N + col) = o;
        }
    }
}

// ---------------- recurrent LSTM scan: 1 CTA per sequence ----------------
// 128 CTAs: dir = blk>>6, b = blk&63. 512 threads, one gate column each.
// Weights: k 0..79 register-resident (80 regs), k 80..127 in dynamic smem.
extern __shared__ float swgt[];   // [SG][512][4] = 96 KB

__global__ __launch_bounds__(512, 1) void lstm_scan(int layer) {
    int tid = threadIdx.x;
    int dir = blockIdx.x >> 6;
    int b = blockIdx.x & 63;
    int seg = layer * 2 + dir;

    __shared__ __align__(16) float sh_h[128];
    __shared__ __align__(16) float gbuf[512];

    // ---- stage smem weight groups RG..31 ----
    {
        const float4* src = (const float4*)(g_wpk + (size_t)seg * 65536 + RG * 2048);
        float4* dst = (float4*)swgt;
        for (int j = tid; j < SG * 512; j += 512) dst[j] = src[j];
    }
    // ---- register weight groups 0..RG-1 ----
    ulonglong2 warr[RG];
    {
        const float* wb = g_wpk + (size_t)seg * 65536 + tid * 4;
#pragma unroll
        for (int i = 0; i < RG; i++) warr[i] = *(const ulonglong2*)(wb + i * 2048);
    }
    if (tid < 128) sh_h[tid] = 0.f;
    __syncthreads();

    const float* zcol = g_zx + ((size_t)dir * B_ + b) * T_ * G_ + tid;
    const int mbase = b * T_;
    float zpre, mpre = 0.f;
    {
        int te0 = dir ? (T_ - 1) : 0;
        zpre = zcol[(size_t)te0 * G_];
        if (tid < 128) mpre = g_mask[mbase + te0];
    }
    float c_state = 0.f;

    for (int t = 0; t < T_; t++) {
        int te = dir ? (T_ - 1 - t) : t;

        // prefetch next step's z (+mask)
        float znext = 0.f, mnext = 0.f;
        if (t + 1 < T_) {
            int tn = dir ? (T_ - 2 - t) : (t + 1);
            znext = zcol[(size_t)tn * G_];
            if (tid < 128) mnext = g_mask[mbase + tn];
        }

        // ---- matvec: two independent FMA2 chains (reg half / smem half) ----
        unsigned long long accA = 0ull, accB = 0ull;
        const float* swp = swgt + tid * 4;
#pragma unroll
        for (int i = 0; i < RG; i++) {
            ulonglong2 h = *(const ulonglong2*)(sh_h + i * 4);
            FMA2(accA, warr[i].x, h.x);
            FMA2(accA, warr[i].y, h.y);
        }
#pragma unroll
        for (int g = 0; g < SG; g++) {
            ulonglong2 w = *(const ulonglong2*)(swp + g * 2048);
            ulonglong2 h = *(const ulonglong2*)(sh_h + RG * 4 + g * 4);
            FMA2(accB, w.x, h.x);
            FMA2(accB, w.y, h.y);
        }
        unsigned long long accT;
        ADD2(accT, accA, accB);
        gbuf[tid] = zpre + f32x2_sum(accT);
        __syncthreads();

        // ---- elementwise LSTM cell (threads 0..127) ----
        if (tid < 128) {
            float vi = gbuf[tid];
            float vf = gbuf[128 + tid];
            float vg = gbuf[256 + tid];
            float vo = gbuf[384 + tid];
            float si = 1.f / (1.f + __expf(-vi));
            float sf = 1.f / (1.f + __expf(-vf));
            float so = 1.f / (1.f + __expf(-vo));
            float cn = sf * c_state + si * tanhf(vg);
            float hn = so * tanhf(cn);
            float hprev = sh_h[tid];
            bool mm = (mpre != 0.f);
            c_state = mm ? cn : c_state;
            float hnew = mm ? hn : hprev;
            sh_h[tid] = hnew;
            if (layer == 0)
                g_h1[((size_t)(b) * T_ + te) * (2 * U_) + dir * U_ + tid] = hnew;
        }
        zpre = znext; mpre = mnext;
        __syncthreads();
    }

    if (layer == 1 && tid < 128)
        g_h2[b * (2 * U_) + dir * U_ + tid] = sh_h[tid];
}

// ---------------- head ----------------
__global__ __launch_bounds__(128) void head_kernel(
    const float* __restrict__ Wd, const float* __restrict__ bd,
    const float* __restrict__ Ws, const float* __restrict__ bs,
    float* __restrict__ out) {
    int b = blockIdx.x, u = threadIdx.x;
    float acc = bd[u];
    const float* h2 = g_h2 + b * (2 * U_);
#pragma unroll 8
    for (int j = 0; j < 2 * U_; j++) acc = fmaf(h2[j], Wd[j * U_ + u], acc);
    acc = fmaxf(acc, 0.f);
    float s = acc * Ws[u];
    __shared__ float red[128];
    red[u] = s;
    __syncthreads();
    for (int off = 64; off; off >>= 1) {
        if (u < off) red[u] += red[u + off];
        __syncthreads();
    }
    if (u == 0) out[b] = 1.f / (1.f + expf(-(red[0] + bs[0])));
}

// ---------------- launch ----------------
extern "C" void kernel_launch(void* const* d_in, const int* in_sizes, int n_in,
                              void* d_out, int out_size) {
    const float* x    = (const float*)d_in[0];
    const float* W1fi = (const float*)d_in[1];
    const float* W1fh = (const float*)d_in[2];
    const float* b1f  = (const float*)d_in[3];
    const float* W1bi = (const float*)d_in[4];
    const float* W1bh = (const float*)d_in[5];
    const float* b1b  = (const float*)d_in[6];
    const float* W2fi = (const float*)d_in[7];
    const float* W2fh = (const float*)d_in[8];
    const float* b2f  = (const float*)d_in[9];
    const float* W2bi = (const float*)d_in[10];
    const float* W2bh = (const float*)d_in[11];
    const float* b2b  = (const float*)d_in[12];
    const float* Wd   = (const float*)d_in[13];
    const float* bd   = (const float*)d_in[14];
    const float* Ws   = (const float*)d_in[15];
    const float* bs   = (const float*)d_in[16];

    const int SWB = SG * 2048 * 4;   // 96 KB dynamic smem
    static int attrDone = 0;
    if (!attrDone) {
        cudaFuncSetAttribute(lstm_scan, cudaFuncAttributeMaxDynamicSharedMemorySize, SWB);
        attrDone = 1;
    }

    int prepWork = B_ * T_ + 4 * G_ * U_;
    prep_kernel<<<(prepWork + 255) / 256, 256>>>(x, W1fh, W1bh, W2fh, W2bh);

    dim3 ggrid(G_ / 128, (B_ * T_) / 128);  // (4, 256)

    sgemm_bias<<<ggrid, 256>>>(x, 0, W1fi, b1f, 0, B_ * T_, G_, F_);
    sgemm_bias<<<ggrid, 256>>>(x, 0, W1bi, b1b, 1, B_ * T_, G_, F_);
    lstm_scan<<<128, 512, SWB>>>(0);

    sgemm_bias<<<ggrid, 256>>>(nullptr, 1, W2fi, b2f, 0, B_ * T_, G_, 2 * U_);
    sgemm_bias<<<ggrid, 256>>>(nullptr, 1, W2bi, b2b, 1, B_ * T_, G_, 2 * U_);
    lstm_scan<<<128, 512, SWB>>>(1);

    head_kernel<<<64, 128>>>(Wd, bd, Ws, bs, (float*)d_out);
}

// round 8
// speedup vs baseline: 1.5735x; 1.0793x over previous
#include <cuda_runtime.h>
#include <math.h>
#include <stdint.h>

#define B_ 64
#define T_ 512
#define F_ 64
#define U_ 128
#define G_ 512   // 4*U

#define RGQ 18   // weight quads (4 floats) per thread in registers
#define SGQ 14   // weight quads per thread in smem (RGQ+SGQ = 32)

// ---------------- scratch (static device memory; no allocations) ----------------
__device__ float g_mask[B_ * T_];
__device__ float g_zx[2u * B_ * T_ * G_];               // layer1 then layer2 (reused)
__device__ float g_h1[B_ * T_ * 2 * U_];
__device__ float g_h2[B_ * 2 * U_];
// packed recurrent weights, quad layout:
// g_wq[seg*65536 + (m*512 + tid)*4 + e], m = gate*8 + g, tid = u*4 + q,
// holding w[k = 32q + 4g + e][col = gate*128 + u]
__device__ float g_wq[4 * G_ * U_];

// ---------------- helpers ----------------
#define FMA2(acc, a, b) asm("fma.rn.f32x2 %0, %1, %2, %0;" : "+l"(acc) : "l"(a), "l"(b))

__device__ __forceinline__ float f32x2_sum(unsigned long long v) {
    unsigned lo, hi;
    asm("mov.b64 {%0, %1}, %2;" : "=r"(lo), "=r"(hi) : "l"(v));
    return __uint_as_float(lo) + __uint_as_float(hi);
}

// ---------------- prep: mask + weight quad-packing ----------------
__global__ void prep_kernel(const float* __restrict__ x,
                            const float* __restrict__ w1f, const float* __restrict__ w1b,
                            const float* __restrict__ w2f, const float* __restrict__ w2b) {
    int i = blockIdx.x * blockDim.x + threadIdx.x;
    if (i < B_ * T_) {
        const float4* row = (const float4*)(x + (size_t)i * F_);
        bool nz = false;
#pragma unroll
        for (int k = 0; k < F_ / 4; k++) {
            float4 v = row[k];
            nz = nz || (v.x != 0.f) || (v.y != 0.f) || (v.z != 0.f) || (v.w != 0.f);
        }
        g_mask[i] = nz ? 1.f : 0.f;
    }
    int j2 = i - B_ * T_;
    if (j2 >= 0 && j2 < 4 * G_ * U_) {
        int w = j2 >> 16;
        int r = j2 & 65535;
        int k = r >> 9;            // 0..127
        int col = r & 511;         // 0..511
        const float* src = (w == 0) ? w1f : (w == 1) ? w1b : (w == 2) ? w2f : w2b;
        int u = col & 127, gate = col >> 7;
        int q = k >> 5, g = (k >> 2) & 7, e = k & 3;
        int tid2 = u * 4 + q;
        int m = gate * 8 + g;
        g_wq[w * 65536 + (m * 512 + tid2) * 4 + e] = src[r];
    }
}

// ---------------- tiled fp32 GEMM with bias (R6 version) ----------------
__global__ __launch_bounds__(256) void sgemm_bias(
    const float* __restrict__ Aext, int useH1,
    const float* __restrict__ W, const float* __restrict__ bias,
    int dirOff, int M, int N, int K) {
    __shared__ float As[16][132];
    __shared__ float Bs[16][128];
    const float* A = useH1 ? g_h1 : Aext;
    float* C = g_zx + (size_t)dirOff * B_ * T_ * G_;

    int tid = threadIdx.x;
    int nBase = blockIdx.x * 128;
    int mBase = blockIdx.y * 128;
    int tx = tid & 15, ty = tid >> 4;
    float acc[8][8];
#pragma unroll
    for (int i = 0; i < 8; i++)
#pragma unroll
        for (int j = 0; j < 8; j++) acc[i][j] = 0.f;

    for (int k0 = 0; k0 < K; k0 += 16) {
#pragma unroll
        for (int s = 0; s < 2; s++) {
            int slot = tid + s * 256;
            int row = slot >> 2, c4 = slot & 3;
            float4 v = *(const float4*)(A + (size_t)(mBase + row) * K + k0 + c4 * 4);
            As[c4 * 4 + 0][row] = v.x;
            As[c4 * 4 + 1][row] = v.y;
            As[c4 * 4 + 2][row] = v.z;
            As[c4 * 4 + 3][row] = v.w;
        }
#pragma unroll
        for (int s = 0; s < 2; s++) {
            int slot = tid + s * 256;
            int row = slot >> 5, c4 = slot & 31;
            *(float4*)(&Bs[row][c4 * 4]) =
                *(const float4*)(W + (size_t)(k0 + row) * N + nBase + c4 * 4);
        }
        __syncthreads();
#pragma unroll
        for (int k = 0; k < 16; k++) {
            float a[8], b[8];
            *(float4*)(a)     = *(const float4*)&As[k][ty * 8];
            *(float4*)(a + 4) = *(const float4*)&As[k][ty * 8 + 4];
            *(float4*)(b)     = *(const float4*)&Bs[k][tx * 8];
            *(float4*)(b + 4) = *(const float4*)&Bs[k][tx * 8 + 4];
#pragma unroll
            for (int i = 0; i < 8; i++)
#pragma unroll
                for (int j = 0; j < 8; j++) acc[i][j] = fmaf(a[i], b[j], acc[i][j]);
        }
        __syncthreads();
    }
#pragma unroll
    for (int i = 0; i < 8; i++) {
        int row = mBase + ty * 8 + i;
#pragma unroll
        for (int j = 0; j < 8; j += 4) {
            int col = nBase + tx * 8 + j;
            float4 o;
            o.x = acc[i][j + 0] + bias[col + 0];
            o.y = acc[i][j + 1] + bias[col + 1];
            o.z = acc[i][j + 2] + bias[col + 2];
            o.w = acc[i][j + 3] + bias[col + 3];
            *(float4*)(C + (size_t)row * N + col) = o;
        }
    }
}

// ---------------- recurrent LSTM scan: shuffle-cell, 1 CTA per sequence ----------------
// 128 CTAs: dir = blk>>6, b = blk&63. 512 threads: u = tid>>2 (unit), q = tid&3 (k-quarter).
// Each thread: quarter-dots for all 4 gates of unit u; butterfly over the 4-lane group;
// cell computed redundantly in the group; h double-buffered (4 bank-staggered copies).
extern __shared__ float swq[];   // [SGQ][512][4] = SGQ*8KB

__global__ __launch_bounds__(512, 1) void lstm_scan(int layer) {
    int tid = threadIdx.x;
    int dir = blockIdx.x >> 6;
    int b = blockIdx.x & 63;
    int seg = layer * 2 + dir;
    int u = tid >> 2, q = tid & 3;

    // 4 copies of h per buffer, copy q at float offset q*136 (bank-staggered)
    __shared__ __align__(16) float hbuf[2][544];

    // ---- stage smem weight quads RGQ..31 ----
    {
        const float4* src = (const float4*)(g_wq + (size_t)seg * 65536 + RGQ * 2048);
        float4* dst = (float4*)swq;
        for (int j = tid; j < SGQ * 512; j += 512) dst[j] = src[j];
    }
    // ---- register weight quads 0..RGQ-1 ----
    ulonglong2 wreg[RGQ];
    {
        const float* wb = g_wq + (size_t)seg * 65536 + tid * 4;
#pragma unroll
        for (int m = 0; m < RGQ; m++) wreg[m] = *(const ulonglong2*)(wb + m * 2048);
    }
    for (int j = tid; j < 1088; j += 512) ((float*)hbuf)[j] = 0.f;
    __syncthreads();

    // z column for this thread: gate q, unit u
    const float* zc = g_zx + ((size_t)dir * B_ + b) * T_ * G_ + q * 128 + u;
    const int mb = b * T_;
    float zpre, mpre;
    {
        int te0 = dir ? (T_ - 1) : 0;
        zpre = zc[(size_t)te0 * G_];
        mpre = g_mask[mb + te0];
    }
    float c_state = 0.f, hprev = 0.f;

    for (int t = 0; t < T_; t++) {
        int te = dir ? (T_ - 1 - t) : t;
        int cur = t & 1, nxt = cur ^ 1;

        // prefetch next step's z/mask (issued ~full step before use)
        float znext = 0.f, mnext = 0.f;
        if (t + 1 < T_) {
            int tn = dir ? (T_ - 2 - t) : (t + 1);
            znext = zc[(size_t)tn * G_];
            mnext = g_mask[mb + tn];
        }

        // ---- load own h quarter (8 x 16B, conflict-free broadcast) ----
        ulonglong2 harr[8];
        const float* hc = &hbuf[cur][q * 168];   // bytes: q*672 + g*16
#pragma unroll
        for (int g = 0; g < 8; g++) harr[g] = *(const ulonglong2*)(hc + 4 * g);

        // ---- quarter-dots for all 4 gates ----
        unsigned long long acc[4] = {0ull, 0ull, 0ull, 0ull};
#pragma unroll
        for (int m = 0; m < RGQ; m++) {
            int j = m >> 3, g = m & 7;
            FMA2(acc[j], wreg[m].x, harr[g].x);
            FMA2(acc[j], wreg[m].y, harr[g].y);
        }
        const float* swp = swq + tid * 4;
#pragma unroll
        for (int s = 0; s < SGQ; s++) {
            int m = RGQ + s;
            int j = m >> 3, g = m & 7;
            ulonglong2 w = *(const ulonglong2*)(swp + s * 2048);
            FMA2(acc[j], w.x, harr[g].x);
            FMA2(acc[j], w.y, harr[g].y);
        }
        float v0 = f32x2_sum(acc[0]);
        float v1 = f32x2_sum(acc[1]);
        float v2 = f32x2_sum(acc[2]);
        float v3 = f32x2_sum(acc[3]);
        // add z into own gate's partial (z counted exactly once per gate)
        v0 += (q == 0) ? zpre : 0.f;
        v1 += (q == 1) ? zpre : 0.f;
        v2 += (q == 2) ? zpre : 0.f;
        v3 += (q == 3) ? zpre : 0.f;

        // ---- butterfly over the 4-lane group ----
        v0 += __shfl_xor_sync(0xFFFFFFFFu, v0, 1);
        v1 += __shfl_xor_sync(0xFFFFFFFFu, v1, 1);
        v2 += __shfl_xor_sync(0xFFFFFFFFu, v2, 1);
        v3 += __shfl_xor_sync(0xFFFFFFFFu, v3, 1);
        v0 += __shfl_xor_sync(0xFFFFFFFFu, v0, 2);
        v1 += __shfl_xor_sync(0xFFFFFFFFu, v1, 2);
        v2 += __shfl_xor_sync(0xFFFFFFFFu, v2, 2);
        v3 += __shfl_xor_sync(0xFFFFFFFFu, v3, 2);

        // ---- cell (redundant in all 4 lanes; identical arithmetic) ----
        float si = 1.f / (1.f + __expf(-v0));
        float sf = 1.f / (1.f + __expf(-v1));
        float so = 1.f / (1.f + __expf(-v3));
        float cn = sf * c_state + si * tanhf(v2);
        float hn = so * tanhf(cn);
        bool mm = (mpre != 0.f);
        c_state = mm ? cn : c_state;
        float hnew = mm ? hn : hprev;
        hbuf[nxt][q * 136 + u] = hnew;   // lane q updates copy q
        if (layer == 0 && q == 0)
            g_h1[((size_t)b * T_ + te) * (2 * U_) + dir * U_ + u] = hnew;
        hprev = hnew;
        zpre = znext;
        mpre = mnext;
        __syncthreads();
    }

    if (layer == 1 && q == 0)
        g_h2[b * (2 * U_) + dir * U_ + u] = hprev;
}

// ---------------- head ----------------
__global__ __launch_bounds__(128) void head_kernel(
    const float* __restrict__ Wd, const float* __restrict__ bd,
    const float* __restrict__ Ws, const float* __restrict__ bs,
    float* __restrict__ out) {
    int b = blockIdx.x, u = threadIdx.x;
    float acc = bd[u];
    const float* h2 = g_h2 + b * (2 * U_);
#pragma unroll 8
    for (int j = 0; j < 2 * U_; j++) acc = fmaf(h2[j], Wd[j * U_ + u], acc);
    acc = fmaxf(acc, 0.f);
    float s = acc * Ws[u];
    __shared__ float red[128];
    red[u] = s;
    __syncthreads();
    for (int off = 64; off; off >>= 1) {
        if (u < off) red[u] += red[u + off];
        __syncthreads();
    }
    if (u == 0) out[b] = 1.f / (1.f + expf(-(red[0] + bs[0])));
}

// ---------------- launch ----------------
extern "C" void kernel_launch(void* const* d_in, const int* in_sizes, int n_in,
                              void* d_out, int out_size) {
    const float* x    = (const float*)d_in[0];
    const float* W1fi = (const float*)d_in[1];
    const float* W1fh = (const float*)d_in[2];
    const float* b1f  = (const float*)d_in[3];
    const float* W1bi = (const float*)d_in[4];
    const float* W1bh = (const float*)d_in[5];
    const float* b1b  = (const float*)d_in[6];
    const float* W2fi = (const float*)d_in[7];
    const float* W2fh = (const float*)d_in[8];
    const float* b2f  = (const float*)d_in[9];
    const float* W2bi = (const float*)d_in[10];
    const float* W2bh = (const float*)d_in[11];
    const float* b2b  = (const float*)d_in[12];
    const float* Wd   = (const float*)d_in[13];
    const float* bd   = (const float*)d_in[14];
    const float* Ws   = (const float*)d_in[15];
    const float* bs   = (const float*)d_in[16];

    const int SWB = SGQ * 2048 * 4;   // dynamic smem for weight quads
    static int attrDone = 0;
    if (!attrDone) {
        cudaFuncSetAttribute(lstm_scan, cudaFuncAttributeMaxDynamicSharedMemorySize, SWB);
        attrDone = 1;
    }

    int prepWork = B_ * T_ + 4 * G_ * U_;
    prep_kernel<<<(prepWork + 255) / 256, 256>>>(x, W1fh, W1bh, W2fh, W2bh);

    dim3 ggrid(G_ / 128, (B_ * T_) / 128);  // (4, 256)

    sgemm_bias<<<ggrid, 256>>>(x, 0, W1fi, b1f, 0, B_ * T_, G_, F_);
    sgemm_bias<<<ggrid, 256>>>(x, 0, W1bi, b1b, 1, B_ * T_, G_, F_);
    lstm_scan<<<128, 512, SWB>>>(0);

    sgemm_bias<<<ggrid, 256>>>(nullptr, 1, W2fi, b2f, 0, B_ * T_, G_, 2 * U_);
    sgemm_bias<<<ggrid, 256>>>(nullptr, 1, W2bi, b2b, 1, B_ * T_, G_, 2 * U_);
    lstm_scan<<<128, 512, SWB>>>(1);

    head_kernel<<<64, 128>>>(Wd, bd, Ws, bs, (float*)d_out);
}